// round 16
// baseline (speedup 1.0000x reference)
#include <cuda_runtime.h>
#include <cuda_bf16.h>

// FM_12060268167845: factorization machine forward.
//   d_in[0] idx  i32 [B,K], d_in[1] x f32 [B,K], d_in[2] b f32 [B,K],
//   d_in[3] w f32 [1M,1], d_in[4] V f32 [1M,128], d_in[5] bias f32 [1]
// out f32 [B] = sigmoid(bias + Xw + 0.5/sum(x) * sum_f((XV)^2 - X2V2))
//
// v15 = v13 (dual per-row sorted streams, batch-interleaved U=10, ld.cg;
// LTS-throughput-bound at ~95% of the ~10.7TB/s L2 service cap) with the
// consume phase rewritten in packed f32x2 (FFMA2):
//   - V rows loaded as v2.u64 (native packed pairs, zero mov overhead)
//   - x stored pre-duplicated {x,x} in smem -> one LDS.64, no packing
//   - per element: 2 FFMA2 (a1) + 2 MUL2+FFMA2 (a2) = 6 packed ops
//     vs ~11 scalar slots before; accumulators 9 -> 6 regs
// Same fp32 math (a2 accumulated per-component instead of via row-norm).

#define FM_B 8192
#define FM_K 200
#define FM_F 128
#define WARPS 4
#define THREADS (WARPS * 32)
#define U 10                       // FM_K % U == 0 (20 batches per row)
#define NBIN 8
#define BIN_SHIFT 26               // 64MB slices of the 512MB V table
#define CHUNKS 7                   // ceil(200/32)

#define FMA2(d, a, b, c) \
    asm("fma.rn.f32x2 %0, %1, %2, %3;" : "=l"(d) : "l"(a), "l"(b), "l"(c))
#define MUL2(d, a, b) \
    asm("mul.rn.f32x2 %0, %1, %2;" : "=l"(d) : "l"(a), "l"(b))

__device__ __forceinline__ void ldcg_v2u64(unsigned long long& lo,
                                           unsigned long long& hi,
                                           const char* p)
{
    asm("ld.global.cg.v2.u64 {%0, %1}, [%2];"
        : "=l"(lo), "=l"(hi) : "l"(p));
}

__global__ __launch_bounds__(THREADS, 8)
void fm_kernel(const int* __restrict__ idx,
               const float* __restrict__ x_vals,
               const float* __restrict__ b_vals,
               const float* __restrict__ w,
               const float* __restrict__ V,
               const float* __restrict__ bias,
               float* __restrict__ out)
{
    const int warp = threadIdx.x >> 5;
    const int lane = threadIdx.x & 31;
    const unsigned lt_mask = (1u << lane) - 1u;

    __shared__ unsigned           s_off[WARPS][2][FM_K];
    __shared__ unsigned long long s_xx[WARPS][2][FM_K];   // {x,x} packed
    __shared__ float              s_scal[WARPS][4];       // xwA,sxA,xwB,sxB

    const int gwarp = blockIdx.x * WARPS + warp;   // 0..4095
    const int bA    = gwarp * 2;                   // rows bA, bA+1

    // ---- per-row: stage + ballot bin-sort ----
    for (int r = 0; r < 2; ++r) {
        const int base = (bA + r) * FM_K;

        unsigned eoff[CHUNKS];
        float    ex[CHUNKS];
        float xw = 0.0f, sx = 0.0f;
        #pragma unroll
        for (int c = 0; c < CHUNKS; ++c) {
            int k = c * 32 + lane;
            if (k < FM_K) {
                int   id = idx[base + k];
                float xv = x_vals[base + k];
                eoff[c] = (unsigned)id * (FM_F * 4u);    // id * 512 bytes
                ex[c]   = xv;
                sx += xv;
                xw = fmaf(b_vals[base + k], __ldg(&w[id]), xw);
            } else {
                eoff[c] = 0xFFFFFFFFu;                   // sentinel: no bin
                ex[c]   = 0.0f;
            }
        }

        #pragma unroll
        for (int o = 16; o > 0; o >>= 1) {
            xw += __shfl_down_sync(0xffffffffu, xw, o);
            sx += __shfl_down_sync(0xffffffffu, sx, o);
        }
        if (lane == 0) {
            s_scal[warp][2 * r + 0] = xw;
            s_scal[warp][2 * r + 1] = sx;
        }

        int cnt[NBIN];
        #pragma unroll
        for (int bb = 0; bb < NBIN; ++bb) cnt[bb] = 0;
        #pragma unroll
        for (int c = 0; c < CHUNKS; ++c) {
            unsigned bin = eoff[c] >> BIN_SHIFT;
            #pragma unroll
            for (int bb = 0; bb < NBIN; ++bb)
                cnt[bb] += __popc(__ballot_sync(0xffffffffu, bin == (unsigned)bb));
        }
        int run[NBIN];
        {
            int acc = 0;
            #pragma unroll
            for (int bb = 0; bb < NBIN; ++bb) { run[bb] = acc; acc += cnt[bb]; }
        }
        #pragma unroll
        for (int c = 0; c < CHUNKS; ++c) {
            unsigned bin = eoff[c] >> BIN_SHIFT;
            unsigned xb  = __float_as_uint(ex[c]);
            unsigned long long xxp =
                (unsigned long long)xb | ((unsigned long long)xb << 32);
            #pragma unroll
            for (int bb = 0; bb < NBIN; ++bb) {
                unsigned msk = __ballot_sync(0xffffffffu, bin == (unsigned)bb);
                if (bin == (unsigned)bb) {
                    int pos = run[bb] + __popc(msk & lt_mask);
                    s_off[warp][r][pos] = eoff[c];
                    s_xx[warp][r][pos]  = xxp;
                }
                run[bb] += __popc(msk);
            }
        }
    }
    __syncwarp();

    // ---- batch-interleaved packed-f32x2 mainloop ----
    const char* __restrict__ Vb = (const char*)V;
    const unsigned lane_off = (unsigned)lane << 4;
    const unsigned* __restrict__ offA = s_off[warp][0];
    const unsigned* __restrict__ offB = s_off[warp][1];
    const unsigned long long* __restrict__ xxA = s_xx[warp][0];
    const unsigned long long* __restrict__ xxB = s_xx[warp][1];

    unsigned long long a1loA = 0ull, a1hiA = 0ull, a2pA = 0ull;
    unsigned long long a1loB = 0ull, a1hiB = 0ull, a2pB = 0ull;

    for (int k0 = 0; k0 < FM_K; k0 += U) {
        {   // --- row A batch ---
            unsigned long long vlo[U], vhi[U];
            #pragma unroll
            for (int u = 0; u < U; ++u)
                ldcg_v2u64(vlo[u], vhi[u], Vb + offA[k0 + u] + lane_off);
            #pragma unroll
            for (int u = 0; u < U; ++u) {
                unsigned long long xx = xxA[k0 + u];
                FMA2(a1loA, vlo[u], xx, a1loA);
                FMA2(a1hiA, vhi[u], xx, a1hiA);
                unsigned long long t0, t1;
                MUL2(t0, vlo[u], xx);
                FMA2(a2pA, t0, t0, a2pA);
                MUL2(t1, vhi[u], xx);
                FMA2(a2pA, t1, t1, a2pA);
            }
        }
        {   // --- row B batch ---
            unsigned long long vlo[U], vhi[U];
            #pragma unroll
            for (int u = 0; u < U; ++u)
                ldcg_v2u64(vlo[u], vhi[u], Vb + offB[k0 + u] + lane_off);
            #pragma unroll
            for (int u = 0; u < U; ++u) {
                unsigned long long xx = xxB[k0 + u];
                FMA2(a1loB, vlo[u], xx, a1loB);
                FMA2(a1hiB, vhi[u], xx, a1hiB);
                unsigned long long t0, t1;
                MUL2(t0, vlo[u], xx);
                FMA2(a2pB, t0, t0, a2pB);
                MUL2(t1, vhi[u], xx);
                FMA2(a2pB, t1, t1, a2pB);
            }
        }
    }

    // ---- reductions + outputs ----
    float a1x = __uint_as_float((unsigned)(a1loA));
    float a1y = __uint_as_float((unsigned)(a1loA >> 32));
    float a1z = __uint_as_float((unsigned)(a1hiA));
    float a1w = __uint_as_float((unsigned)(a1hiA >> 32));
    float a20 = __uint_as_float((unsigned)(a2pA));
    float a21 = __uint_as_float((unsigned)(a2pA >> 32));
    float pqA = fmaf(a1x, a1x, fmaf(a1y, a1y,
                fmaf(a1z, a1z, a1w * a1w))) - (a20 + a21);

    a1x = __uint_as_float((unsigned)(a1loB));
    a1y = __uint_as_float((unsigned)(a1loB >> 32));
    a1z = __uint_as_float((unsigned)(a1hiB));
    a1w = __uint_as_float((unsigned)(a1hiB >> 32));
    a20 = __uint_as_float((unsigned)(a2pB));
    a21 = __uint_as_float((unsigned)(a2pB >> 32));
    float pqB = fmaf(a1x, a1x, fmaf(a1y, a1y,
                fmaf(a1z, a1z, a1w * a1w))) - (a20 + a21);

    #pragma unroll
    for (int o = 16; o > 0; o >>= 1) {
        pqA += __shfl_down_sync(0xffffffffu, pqA, o);
        pqB += __shfl_down_sync(0xffffffffu, pqB, o);
    }

    if (lane == 0) {
        float bia = bias[0];
        float pA  = 0.5f * (1.0f / s_scal[warp][1]) * pqA;
        out[bA]     = 1.0f / (1.0f + __expf(-(bia + s_scal[warp][0] + pA)));
        float pB  = 0.5f * (1.0f / s_scal[warp][3]) * pqB;
        out[bA + 1] = 1.0f / (1.0f + __expf(-(bia + s_scal[warp][2] + pB)));
    }
}

extern "C" void kernel_launch(void* const* d_in, const int* in_sizes, int n_in,
                              void* d_out, int out_size)
{
    const int*   idx    = (const int*)d_in[0];
    const float* x_vals = (const float*)d_in[1];
    const float* b_vals = (const float*)d_in[2];
    const float* w      = (const float*)d_in[3];
    const float* V      = (const float*)d_in[4];
    const float* bias   = (const float*)d_in[5];
    float*       out    = (float*)d_out;
    (void)in_sizes; (void)n_in; (void)out_size;

    const int grid = FM_B / (WARPS * 2);   // 1024 CTAs: one resident wave
    fm_kernel<<<grid, THREADS>>>(idx, x_vals, b_vals, w, V, bias, out);
}